// round 14
// baseline (speedup 1.0000x reference)
#include <cuda_runtime.h>
#include <cstdint>
#include <math.h>

// Problem constants (fixed by the dataset)
#define TT   16384          // tokens = 8*2048
#define DD   768
#define EE   4
#define DFFC 1024

// -------- scratch (no cudaMalloc allowed) --------
__device__ uint32_t g_h[TT * DD];                  // projection output (tf32 bits)
__device__ uint32_t g_act[(size_t)EE * TT * DFFC]; // per-expert gelu activations (tf32 bits)
__device__ uint32_t g_Xr[TT * DD];                 // X pre-rounded to tf32 bits
__device__ uint32_t g_Wt[DD * DD];                 // W^T  as tf32 bits  [n=DD][k=DD]
__device__ uint32_t g_W1t[(size_t)EE * DFFC * DD]; // W1^T as tf32 bits  [e][n=DFF][k=DD]
__device__ uint32_t g_W2t[(size_t)EE * DD * DFFC]; // W2^T as tf32 bits  [e][n=DD][k=DFF]
__device__ int      g_idx[EE * TT];                // compacted row -> original token
__device__ float    g_gate[EE * TT];               // compacted row -> gate
__device__ int      g_cnt[EE + 1];                 // per-expert counts; [EE] = T
__device__ float    g_Wf[DD * 4];                  // fused router weight W @ Wg
__device__ float    g_bf[4];                       // fused router bias b @ Wg + bg

// -------- helpers --------
__device__ __forceinline__ uint32_t f32_to_tf32(float x) {
    uint32_t u;
    asm("cvt.rna.tf32.f32 %0, %1;" : "=r"(u) : "f"(x));
    return u;
}

__device__ __forceinline__ float gelu_tanh(float x) {
    float x3 = x * x * x;
    return 0.5f * x * (1.0f + tanhf(0.7978845608028654f * (x + 0.044715f * x3)));
}

__device__ __forceinline__ void mma_tf32(float c[4], const uint32_t a[4], const uint32_t b[2]) {
    asm volatile(
        "mma.sync.aligned.m16n8k8.row.col.f32.tf32.tf32.f32 "
        "{%0,%1,%2,%3}, {%4,%5,%6,%7}, {%8,%9}, {%0,%1,%2,%3};\n"
        : "+f"(c[0]), "+f"(c[1]), "+f"(c[2]), "+f"(c[3])
        : "r"(a[0]), "r"(a[1]), "r"(a[2]), "r"(a[3]), "r"(b[0]), "r"(b[1]));
}

// vector f32x2 global reduction (no return); 2 adds per element on zeroed buf
// -> bit-deterministic regardless of atomic order.
__device__ __forceinline__ void red_add_v2(float* p, float x, float y) {
    asm volatile(
        "{\n\t.reg .u64 pg;\n\t"
        "cvta.to.global.u64 pg, %0;\n\t"
        "red.global.add.v2.f32 [pg], {%1, %2};\n\t}"
        :: "l"(p), "f"(x), "f"(y) : "memory");
}

__device__ __forceinline__ uint32_t smem_u32(const void* p) {
    uint32_t a;
    asm("{ .reg .u64 t; cvta.to.shared.u64 t, %1; cvt.u32.u64 %0, t; }" : "=r"(a) : "l"(p));
    return a;
}

#define CP_ASYNC16(dst_u32, gptr) \
    asm volatile("cp.async.cg.shared.global [%0], [%1], 16;\n" \
                 :: "r"(dst_u32), "l"(gptr))
#define CP_COMMIT()      asm volatile("cp.async.commit_group;\n" ::: "memory")
#define CP_WAIT_ALL()    asm volatile("cp.async.wait_group 0;\n" ::: "memory")

// ldmatrix x4: four 8x8 b16 matrices; for tf32 data each lane's reg j holds the
// 4-byte word (L%4) of 16B-row (L/4) of matrix j  ->  exactly the m16n8k8 frag.
#define LDSM_X4(r0, r1, r2, r3, addr) \
    asm volatile("ldmatrix.sync.aligned.m8n8.x4.shared.b16 {%0,%1,%2,%3}, [%4];" \
                 : "=r"(r0), "=r"(r1), "=r"(r2), "=r"(r3) : "r"(addr))

// ============================================================================
// init: zero counters and index/gate lists (pads map to token 0, gate 0)
// ============================================================================
__global__ void init_kernel(int* __restrict__ cnt, int* __restrict__ idxL,
                            float* __restrict__ gateL)
{
    int i = blockIdx.x * blockDim.x + threadIdx.x;
    if (i < EE) cnt[i] = 0;
    if (i == EE) cnt[EE] = TT;
    if (i < EE * TT) { idxL[i] = 0; gateL[i] = 0.0f; }
}

// ============================================================================
// elementwise round-to-tf32 (vec4), n multiple of 4   (X only)
// ============================================================================
__global__ __launch_bounds__(256) void round_tf32_kernel(
    const float* __restrict__ in, uint32_t* __restrict__ out, size_t n4)
{
    size_t i = (size_t)blockIdx.x * blockDim.x + threadIdx.x;
    if (i >= n4) return;
    float4 v = *(const float4*)(in + i * 4);
    uint4 o;
    o.x = f32_to_tf32(v.x); o.y = f32_to_tf32(v.y);
    o.z = f32_to_tf32(v.z); o.w = f32_to_tf32(v.w);
    *(uint4*)(out + i * 4) = o;
}

// ============================================================================
// Tiled transpose + round-to-tf32: out[c][r] = tf32(in[r][c]).
// grid = (C/32, R/32, nbatch), 256 threads.
// ============================================================================
__global__ __launch_bounds__(256) void transpose_tf32_kernel(
    const float* __restrict__ in, uint32_t* __restrict__ out,
    int R, int C, size_t inE, size_t outE)
{
    __shared__ uint32_t tile[32][33];
    in  += blockIdx.z * inE;
    out += blockIdx.z * outE;
    const int c0 = blockIdx.x * 32, r0 = blockIdx.y * 32;
    const int tx = threadIdx.x & 31, ty = threadIdx.x >> 5;
#pragma unroll
    for (int i = ty; i < 32; i += 8)
        tile[i][tx] = f32_to_tf32(in[(size_t)(r0 + i) * C + c0 + tx]);
    __syncthreads();
#pragma unroll
    for (int i = ty; i < 32; i += 8)
        out[(size_t)(c0 + i) * R + r0 + tx] = tile[tx][i];
}

// ============================================================================
// Router-weight fusion: Wf = W @ Wg  [DD,4],  bf = b @ Wg + bg  [4]
// ============================================================================
__global__ __launch_bounds__(256) void fuse_wg_kernel(
    const float* __restrict__ W, const float* __restrict__ Wg,
    const float* __restrict__ b, const float* __restrict__ bg,
    float* __restrict__ Wf, float* __restrict__ bf)
{
    int warp = (blockIdx.x * blockDim.x + threadIdx.x) >> 5;
    int lane = threadIdx.x & 31;
    if (warp > DD) return;

    const float* row = (warp < DD) ? (W + (size_t)warp * DD) : b;

    float a0 = 0.f, a1 = 0.f, a2 = 0.f, a3 = 0.f;
    for (int e = lane; e < DD; e += 32) {
        float w = row[e];
        float4 wg = *(const float4*)&Wg[(size_t)e * 4];
        a0 += w * wg.x; a1 += w * wg.y; a2 += w * wg.z; a3 += w * wg.w;
    }
#pragma unroll
    for (int o = 16; o > 0; o >>= 1) {
        a0 += __shfl_xor_sync(0xffffffffu, a0, o);
        a1 += __shfl_xor_sync(0xffffffffu, a1, o);
        a2 += __shfl_xor_sync(0xffffffffu, a2, o);
        a3 += __shfl_xor_sync(0xffffffffu, a3, o);
    }
    if (lane == 0) {
        if (warp < DD) {
            *(float4*)&Wf[(size_t)warp * 4] = make_float4(a0, a1, a2, a3);
        } else {
            bf[0] = a0 + bg[0]; bf[1] = a1 + bg[1];
            bf[2] = a2 + bg[2]; bf[3] = a3 + bg[3];
        }
    }
}

// ============================================================================
// Router: one warp per token, fp32 logits straight from X via fused Wf/bf.
// ============================================================================
__global__ __launch_bounds__(256) void router_kernel(
    const float* __restrict__ X, const float* __restrict__ Wf,
    const float* __restrict__ bf, int* __restrict__ idxL,
    float* __restrict__ gateL, int* __restrict__ cnt, int T)
{
    int tok  = (blockIdx.x * blockDim.x + threadIdx.x) >> 5;
    int lane = threadIdx.x & 31;
    if (tok >= T) return;
    const float* xr = X + (size_t)tok * DD;

    float a0 = 0.f, a1 = 0.f, a2 = 0.f, a3 = 0.f;
    for (int d = lane; d < DD; d += 32) {
        float xv = xr[d];
        float4 w = *(const float4*)&Wf[(size_t)d * 4];
        a0 += xv * w.x; a1 += xv * w.y; a2 += xv * w.z; a3 += xv * w.w;
    }
#pragma unroll
    for (int o = 16; o > 0; o >>= 1) {
        a0 += __shfl_xor_sync(0xffffffffu, a0, o);
        a1 += __shfl_xor_sync(0xffffffffu, a1, o);
        a2 += __shfl_xor_sync(0xffffffffu, a2, o);
        a3 += __shfl_xor_sync(0xffffffffu, a3, o);
    }
    if (lane == 0) {
        float l[4] = {a0 + bf[0], a1 + bf[1], a2 + bf[2], a3 + bf[3]};
        int i1 = 0;
#pragma unroll
        for (int e = 1; e < 4; e++) if (l[e] > l[i1]) i1 = e;
        int i2 = (i1 == 0) ? 1 : 0;
#pragma unroll
        for (int e = 0; e < 4; e++) if (e != i1 && l[e] > l[i2]) i2 = e;
        float p2 = expf(l[i2] - l[i1]);
        float s  = 1.0f + p2;
        float g1 = 1.0f / s;
        float g2 = p2 / s;

        int p = atomicAdd(&cnt[i1], 1);
        idxL[i1 * TT + p]  = tok;
        gateL[i1 * TT + p] = g1;
        p = atomicAdd(&cnt[i2], 1);
        idxL[i2 * TT + p]  = tok;
        gateL[i2 * TT + p] = g2;
    }
}

// ============================================================================
// TF32 tensor-core GEMM v4: R13's proven schedule (256 thr, 8 warps 4m x 2n,
// warp tile 32x64, CTA 128x128, BK=16, double-buffered cp.async) with BOTH
// operands K-major [128 rows][16 k] stride-20 smem tiles and ldmatrix.x4
// fragment loads (6 ldsm.x4 + 16 mma per k8 vs 24 scalar LDS before).
//   A:  [rows x K] token rows (tf32 bits), optionally gathered via idxL
//   Bt: [N x K]    weight TRANSPOSED (tf32 bits)
// EPI 0: C(u32)[r][c] = tf32bits(v + bias)                 (proj -> h)
// EPI 1: C(u32)[r][c] = tf32bits(gelu(v + bias))           (GEMM1 -> act)
// EPI 2: out(f32)[idx[r]][c] += gate[r]*(v + bias), red.v2 (GEMM2 -> out)
// EBATCH: blockIdx.z = expert, offsets Bt/bias/idxL/gateL/count and A or C.
// ============================================================================
template<bool GATHER, int EPI, bool EBATCH>
__global__ __launch_bounds__(256) void gemm_tf32_v4(
    const uint32_t* __restrict__ A, const uint32_t* __restrict__ Bt,
    const float* __restrict__ bias,
    const int* __restrict__ idxL, const float* __restrict__ gateL,
    const int* __restrict__ countp,
    void* __restrict__ Cv, int N, int K, size_t aE, size_t cE)
{
    __shared__ uint32_t As[2][128][20];    // [row][k], stride 20
    __shared__ uint32_t Bs[2][128][20];    // [n-row][k], stride 20 (same layout)

    if (EBATCH) {
        const int e = blockIdx.z;
        Bt     += (size_t)e * K * N;
        bias   += (size_t)e * N;
        idxL   += e * TT;
        gateL  += e * TT;
        countp += e;
        A      += (size_t)e * aE;
    }
    uint32_t* Cu = (uint32_t*)Cv;
    float*    Cf = (float*)Cv;
    if (EBATCH && EPI == 1) Cu += (size_t)blockIdx.z * cE;

    const int count = *countp;
    const int bm = blockIdx.y * 128;
    if (bm >= count) return;
    const int bn = blockIdx.x * 128;

    const int tid  = threadIdx.x;
    const int warp = tid >> 5, lane = tid & 31;
    const int g    = lane >> 2, tig = lane & 3;
    const int wm   = (warp >> 1) * 32;   // 0,32,64,96
    const int wn   = (warp & 1) * 64;    // 0,64

    float c[2][8][4];
#pragma unroll
    for (int mt = 0; mt < 2; mt++)
#pragma unroll
        for (int nt = 0; nt < 8; nt++)
#pragma unroll
            for (int i = 0; i < 4; i++) c[mt][nt][i] = 0.0f;

    // ---- cp.async fill mapping (identical for A and B tiles) ----
    // 128 rows x 4 segs = 512 chunks; thread t -> (row t>>2, seg t&3) and (+64)
    const int fRow = tid >> 2, fSeg = tid & 3;
    int arow0 = bm + fRow, arow1 = arow0 + 64;
    if (GATHER) { arow0 = idxL[arow0]; arow1 = idxL[arow1]; }   // pads -> token 0
    const uint32_t* aG0 = A  + (size_t)arow0 * K + fSeg * 4;
    const uint32_t* aG1 = A  + (size_t)arow1 * K + fSeg * 4;
    const uint32_t* bG0 = Bt + (size_t)(bn + fRow) * K + fSeg * 4;
    const uint32_t* bG1 = bG0 + (size_t)64 * K;

    const uint32_t smA = smem_u32(&As[0][0][0]);
    const uint32_t smB = smem_u32(&Bs[0][0][0]);
    const uint32_t fOff = (uint32_t)(fRow * 80 + fSeg * 16);
    const uint32_t sA0 = smA + fOff, sA1 = sA0 + 64 * 80;
    const uint32_t sB0 = smB + fOff, sB1 = sB0 + 64 * 80;
    const uint32_t stageB = 128 * 20 * 4;   // 10240 B per stage

    // ---- ldmatrix per-lane addresses ----
    // A matrices (rh,kh) order (0,0),(1,0),(0,1),(1,1):
    //   row = wm + mt*16 + ((lane>>3)&1)*8 + (lane&7); col = ks + (lane>>4)*4
    // B matrices (n-blk,kh) order (2p,0),(2p,1),(2p+1,0),(2p+1,1):
    //   row = wn + p*16 + (lane>>4)*8 + (lane&7);      col = ks + ((lane>>3)&1)*4
    const int lane7 = lane & 7;
    const uint32_t aRowL = ((lane >> 3) & 1) * 8 + lane7;
    const uint32_t aColL = (lane >> 4) * 4;
    const uint32_t bRowL = (lane >> 4) * 8 + lane7;
    const uint32_t bColL = ((lane >> 3) & 1) * 4;
    uint32_t aAddr[2], bAddr[4];
#pragma unroll
    for (int mt = 0; mt < 2; mt++)
        aAddr[mt] = smA + ((wm + mt * 16 + aRowL) * 20 + aColL) * 4;
#pragma unroll
    for (int p = 0; p < 4; p++)
        bAddr[p] = smB + ((wn + p * 16 + bRowL) * 20 + bColL) * 4;

    const int KT = K >> 4;

    // prologue: issue tile 0 into stage 0
    CP_ASYNC16(sA0, aG0);
    CP_ASYNC16(sA1, aG1);
    CP_ASYNC16(sB0, bG0);
    CP_ASYNC16(sB1, bG1);
    CP_COMMIT();

    for (int kt = 0; kt < KT; kt++) {
        const int cur = kt & 1;
        CP_WAIT_ALL();           // tile kt resident in stage cur
        __syncthreads();         // all warps done with stage cur^1

        if (kt + 1 < KT) {       // issue tile kt+1 into stage cur^1 (overlaps mma)
            const uint32_t nbO = (cur ^ 1) * stageB;
            CP_ASYNC16(sA0 + nbO, aG0 + (kt + 1) * 16);
            CP_ASYNC16(sA1 + nbO, aG1 + (kt + 1) * 16);
            CP_ASYNC16(sB0 + nbO, bG0 + (kt + 1) * 16);
            CP_ASYNC16(sB1 + nbO, bG1 + (kt + 1) * 16);
            CP_COMMIT();
        }

        const uint32_t stO = cur * stageB;
#pragma unroll
        for (int ks = 0; ks < 16; ks += 8) {
            uint32_t af[2][4], bf[8][2];
#pragma unroll
            for (int mt = 0; mt < 2; mt++)
                LDSM_X4(af[mt][0], af[mt][1], af[mt][2], af[mt][3],
                        aAddr[mt] + stO + ks * 4);
#pragma unroll
            for (int p = 0; p < 4; p++)
                LDSM_X4(bf[2 * p][0], bf[2 * p][1], bf[2 * p + 1][0], bf[2 * p + 1][1],
                        bAddr[p] + stO + ks * 4);
#pragma unroll
            for (int mt = 0; mt < 2; mt++)
#pragma unroll
                for (int nt = 0; nt < 8; nt++)
                    mma_tf32(c[mt][nt], af[mt], bf[nt]);
        }
    }

    // ---- epilogue (validated R8/R10/R13) ----
#pragma unroll
    for (int mt = 0; mt < 2; mt++) {
        int rc0 = bm + wm + mt * 16 + g;
        int rc1 = rc0 + 8;
        bool v0 = true, v1 = true;
        int row0 = rc0, row1 = rc1;
        float s0 = 1.0f, s1 = 1.0f;
        if (EPI == 2) {
            v0 = rc0 < count;
            v1 = rc1 < count;
            row0 = v0 ? idxL[rc0] : 0;
            row1 = v1 ? idxL[rc1] : 0;
            s0 = v0 ? gateL[rc0] : 0.0f;
            s1 = v1 ? gateL[rc1] : 0.0f;
        }
#pragma unroll
        for (int nt = 0; nt < 8; nt++) {
            int c0 = bn + wn + nt * 8 + tig * 2;
            float b0v = bias[c0], b1v = bias[c0 + 1];
            float v00 = c[mt][nt][0] + b0v;
            float v01 = c[mt][nt][1] + b1v;
            float v10 = c[mt][nt][2] + b0v;
            float v11 = c[mt][nt][3] + b1v;
            if (EPI == 0) {
                size_t o0 = (size_t)row0 * N + c0;
                size_t o1 = (size_t)row1 * N + c0;
                Cu[o0]     = f32_to_tf32(v00);
                Cu[o0 + 1] = f32_to_tf32(v01);
                Cu[o1]     = f32_to_tf32(v10);
                Cu[o1 + 1] = f32_to_tf32(v11);
            } else if (EPI == 1) {
                size_t o0 = (size_t)row0 * N + c0;
                size_t o1 = (size_t)row1 * N + c0;
                Cu[o0]     = f32_to_tf32(gelu_tanh(v00));
                Cu[o0 + 1] = f32_to_tf32(gelu_tanh(v01));
                Cu[o1]     = f32_to_tf32(gelu_tanh(v10));
                Cu[o1 + 1] = f32_to_tf32(gelu_tanh(v11));
            } else {
                if (v0) red_add_v2(Cf + (size_t)row0 * N + c0, s0 * v00, s0 * v01);
                if (v1) red_add_v2(Cf + (size_t)row1 * N + c0, s1 * v10, s1 * v11);
            }
        }
    }
}

// ============================================================================
// launch
// ============================================================================
extern "C" void kernel_launch(void* const* d_in, const int* in_sizes, int n_in,
                              void* d_out, int out_size)
{
    const float* X  = (const float*)d_in[0];   // [8,2048,768]
    const float* W  = (const float*)d_in[1];   // [768,768]
    const float* b  = (const float*)d_in[2];   // [768]
    const float* Wg = (const float*)d_in[3];   // [768,4]
    const float* bg = (const float*)d_in[4];   // [4]
    const float* W1 = (const float*)d_in[5];   // [4,768,1024]
    const float* b1 = (const float*)d_in[6];   // [4,1024]
    const float* W2 = (const float*)d_in[7];   // [4,1024,768]
    const float* b2 = (const float*)d_in[8];   // [4,768]
    float* out = (float*)d_out;

    const int T = in_sizes[0] / DD;            // 16384

    uint32_t *h, *act, *Xr, *Wt, *W1t, *W2t;
    float *gate, *Wf, *bf;
    int *idx, *cnt;
    cudaGetSymbolAddress((void**)&h,    g_h);
    cudaGetSymbolAddress((void**)&act,  g_act);
    cudaGetSymbolAddress((void**)&Xr,   g_Xr);
    cudaGetSymbolAddress((void**)&Wt,   g_Wt);
    cudaGetSymbolAddress((void**)&W1t,  g_W1t);
    cudaGetSymbolAddress((void**)&W2t,  g_W2t);
    cudaGetSymbolAddress((void**)&idx,  g_idx);
    cudaGetSymbolAddress((void**)&gate, g_gate);
    cudaGetSymbolAddress((void**)&cnt,  g_cnt);
    cudaGetSymbolAddress((void**)&Wf,   g_Wf);
    cudaGetSymbolAddress((void**)&bf,   g_bf);

    // 0) zero output (red.v2-accumulated) and routing state
    cudaMemsetAsync(out, 0, sizeof(float) * (size_t)T * DD);
    init_kernel<<<(EE * TT + 255) / 256, 256>>>(cnt, idx, gate);

    // 1) operand prep: round X; transpose+round weights to [n][k] tf32 bits
    {
        size_t nX = (size_t)T * DD / 4;
        round_tf32_kernel<<<(unsigned)((nX + 255) / 256), 256>>>(X, Xr, nX);
        transpose_tf32_kernel<<<dim3(DD / 32, DD / 32, 1), 256>>>(
            W, Wt, DD, DD, 0, 0);
        transpose_tf32_kernel<<<dim3(DFFC / 32, DD / 32, EE), 256>>>(
            W1, W1t, DD, DFFC, (size_t)DD * DFFC, (size_t)DFFC * DD);
        transpose_tf32_kernel<<<dim3(DD / 32, DFFC / 32, EE), 256>>>(
            W2, W2t, DFFC, DD, (size_t)DFFC * DD, (size_t)DD * DFFC);
    }

    // 2) fused router weights + router (fp32 logits straight from X)
    fuse_wg_kernel<<<(DD + 1 + 7) / 8, 256>>>(W, Wg, b, bg, Wf, bf);
    router_kernel<<<T / 8, 256>>>(X, Wf, bf, idx, gate, cnt, T);

    // 3) projection h = X @ W + b      (dense, EPI0 writes tf32 bits)
    gemm_tf32_v4<false, 0, false>
        <<<dim3(DD / 128, T / 128), 256>>>(
            Xr, Wt, b, idx, gate, cnt + EE, h, DD, DD, 0, 0);

    // 4) GEMM1 (all experts): act[e][rc] = tf32(gelu(h[idx[rc]] @ W1[e] + b1[e]))
    gemm_tf32_v4<true, 1, true>
        <<<dim3(DFFC / 128, T / 128, EE), 256>>>(
            h, W1t, b1, idx, gate, cnt, act, DFFC, DD,
            0, (size_t)TT * DFFC);

    // 5) GEMM2 (all experts): out[idx[rc]] += gate[rc]*(act[e][rc] @ W2[e] + b2[e])
    gemm_tf32_v4<false, 2, true>
        <<<dim3(DD / 128, T / 128, EE), 256>>>(
            act, W2t, b2, idx, gate, cnt, out, DD, DFFC,
            (size_t)TT * DFFC, 0);
}

// round 17
// speedup vs baseline: 1.5327x; 1.5327x over previous
#include <cuda_runtime.h>
#include <cuda_fp16.h>
#include <cstdint>
#include <math.h>

// Problem constants (fixed by the dataset)
#define TT   16384          // tokens = 8*2048
#define DD   768
#define EE   4
#define DFFC 1024

// -------- scratch (no cudaMalloc allowed) --------
__device__ uint32_t g_Xh[TT * DD / 2];                 // X as packed f16x2
__device__ uint32_t g_h[TT * DD / 2];                  // projection output (f16x2)
__device__ uint32_t g_act[(size_t)EE * TT * DFFC / 2]; // per-expert gelu act (f16x2)
__device__ uint16_t g_Wt[DD * DD];                     // W^T  f16  [n=DD][k=DD]
__device__ uint16_t g_W1t[(size_t)EE * DFFC * DD];     // W1^T f16  [e][n=DFF][k=DD]
__device__ uint16_t g_W2t[(size_t)EE * DD * DFFC];     // W2^T f16  [e][n=DD][k=DFF]
__device__ int      g_idx[EE * TT];                    // compacted row -> original token
__device__ float    g_gate[EE * TT];                   // compacted row -> gate
__device__ int      g_cnt[EE + 1];                     // per-expert counts; [EE] = T
__device__ float    g_Wf[DD * 4];                      // fused router weight W @ Wg
__device__ float    g_bf[4];                           // fused router bias b @ Wg + bg

// -------- helpers --------
__device__ __forceinline__ float gelu_tanh(float x) {
    float x3 = x * x * x;
    return 0.5f * x * (1.0f + tanhf(0.7978845608028654f * (x + 0.044715f * x3)));
}

__device__ __forceinline__ uint32_t pack_f16x2(float lo, float hi) {
    __half2 h = __floats2half2_rn(lo, hi);   // x = lo (low half), y = hi
    return *(uint32_t*)&h;
}

// m16n8k16 f16 mma, fp32 accumulate
__device__ __forceinline__ void mma_f16(float c[4], const uint32_t a[4], const uint32_t b[2]) {
    asm volatile(
        "mma.sync.aligned.m16n8k16.row.col.f32.f16.f16.f32 "
        "{%0,%1,%2,%3}, {%4,%5,%6,%7}, {%8,%9}, {%0,%1,%2,%3};\n"
        : "+f"(c[0]), "+f"(c[1]), "+f"(c[2]), "+f"(c[3])
        : "r"(a[0]), "r"(a[1]), "r"(a[2]), "r"(a[3]), "r"(b[0]), "r"(b[1]));
}

// vector f32x2 global reduction (no return); 2 adds per element on zeroed buf
// -> bit-deterministic regardless of atomic order.
__device__ __forceinline__ void red_add_v2(float* p, float x, float y) {
    asm volatile(
        "{\n\t.reg .u64 pg;\n\t"
        "cvta.to.global.u64 pg, %0;\n\t"
        "red.global.add.v2.f32 [pg], {%1, %2};\n\t}"
        :: "l"(p), "f"(x), "f"(y) : "memory");
}

__device__ __forceinline__ uint32_t smem_u32(const void* p) {
    uint32_t a;
    asm("{ .reg .u64 t; cvta.to.shared.u64 t, %1; cvt.u32.u64 %0, t; }" : "=r"(a) : "l"(p));
    return a;
}

#define CP_ASYNC16(dst_u32, gptr) \
    asm volatile("cp.async.cg.shared.global [%0], [%1], 16;\n" \
                 :: "r"(dst_u32), "l"(gptr))
#define CP_COMMIT()      asm volatile("cp.async.commit_group;\n" ::: "memory")
#define CP_WAIT_ALL()    asm volatile("cp.async.wait_group 0;\n" ::: "memory")

#define LDSM_X4(r0, r1, r2, r3, addr) \
    asm volatile("ldmatrix.sync.aligned.m8n8.x4.shared.b16 {%0,%1,%2,%3}, [%4];" \
                 : "=r"(r0), "=r"(r1), "=r"(r2), "=r"(r3) : "r"(addr))

// ============================================================================
// init: zero counters and index/gate lists (pads map to token 0, gate 0)
// ============================================================================
__global__ void init_kernel(int* __restrict__ cnt, int* __restrict__ idxL,
                            float* __restrict__ gateL)
{
    int i = blockIdx.x * blockDim.x + threadIdx.x;
    if (i < EE) cnt[i] = 0;
    if (i == EE) cnt[EE] = TT;
    if (i < EE * TT) { idxL[i] = 0; gateL[i] = 0.0f; }
}

// ============================================================================
// elementwise f32 -> packed f16x2 (vec4 in, 2x u32 out)
// ============================================================================
__global__ __launch_bounds__(256) void tofp16_kernel(
    const float* __restrict__ in, uint32_t* __restrict__ out, size_t n4)
{
    size_t i = (size_t)blockIdx.x * blockDim.x + threadIdx.x;
    if (i >= n4) return;
    float4 v = *(const float4*)(in + i * 4);
    uint2 o;
    o.x = pack_f16x2(v.x, v.y);
    o.y = pack_f16x2(v.z, v.w);
    *(uint2*)(out + i * 2) = o;
}

// ============================================================================
// Tiled transpose + convert to f16: out[c][r] = f16(in[r][c]).
// grid = (C/32, R/32, nbatch), 256 threads.
// ============================================================================
__global__ __launch_bounds__(256) void transpose_f16_kernel(
    const float* __restrict__ in, uint16_t* __restrict__ out,
    int R, int C, size_t inE, size_t outE)
{
    __shared__ float tile[32][33];
    in  += blockIdx.z * inE;
    out += blockIdx.z * outE;
    const int c0 = blockIdx.x * 32, r0 = blockIdx.y * 32;
    const int tx = threadIdx.x & 31, ty = threadIdx.x >> 5;
#pragma unroll
    for (int i = ty; i < 32; i += 8)
        tile[i][tx] = in[(size_t)(r0 + i) * C + c0 + tx];
    __syncthreads();
#pragma unroll
    for (int i = ty; i < 32; i += 8) {
        __half hv = __float2half_rn(tile[tx][i]);
        out[(size_t)(c0 + i) * R + r0 + tx] = *(uint16_t*)&hv;
    }
}

// ============================================================================
// Router-weight fusion: Wf = W @ Wg  [DD,4],  bf = b @ Wg + bg  [4]
// ============================================================================
__global__ __launch_bounds__(256) void fuse_wg_kernel(
    const float* __restrict__ W, const float* __restrict__ Wg,
    const float* __restrict__ b, const float* __restrict__ bg,
    float* __restrict__ Wf, float* __restrict__ bf)
{
    int warp = (blockIdx.x * blockDim.x + threadIdx.x) >> 5;
    int lane = threadIdx.x & 31;
    if (warp > DD) return;

    const float* row = (warp < DD) ? (W + (size_t)warp * DD) : b;

    float a0 = 0.f, a1 = 0.f, a2 = 0.f, a3 = 0.f;
    for (int e = lane; e < DD; e += 32) {
        float w = row[e];
        float4 wg = *(const float4*)&Wg[(size_t)e * 4];
        a0 += w * wg.x; a1 += w * wg.y; a2 += w * wg.z; a3 += w * wg.w;
    }
#pragma unroll
    for (int o = 16; o > 0; o >>= 1) {
        a0 += __shfl_xor_sync(0xffffffffu, a0, o);
        a1 += __shfl_xor_sync(0xffffffffu, a1, o);
        a2 += __shfl_xor_sync(0xffffffffu, a2, o);
        a3 += __shfl_xor_sync(0xffffffffu, a3, o);
    }
    if (lane == 0) {
        if (warp < DD) {
            *(float4*)&Wf[(size_t)warp * 4] = make_float4(a0, a1, a2, a3);
        } else {
            bf[0] = a0 + bg[0]; bf[1] = a1 + bg[1];
            bf[2] = a2 + bg[2]; bf[3] = a3 + bg[3];
        }
    }
}

// ============================================================================
// Router: one warp per token, fp32 logits straight from X via fused Wf/bf.
// ============================================================================
__global__ __launch_bounds__(256) void router_kernel(
    const float* __restrict__ X, const float* __restrict__ Wf,
    const float* __restrict__ bf, int* __restrict__ idxL,
    float* __restrict__ gateL, int* __restrict__ cnt, int T)
{
    int tok  = (blockIdx.x * blockDim.x + threadIdx.x) >> 5;
    int lane = threadIdx.x & 31;
    if (tok >= T) return;
    const float* xr = X + (size_t)tok * DD;

    float a0 = 0.f, a1 = 0.f, a2 = 0.f, a3 = 0.f;
    for (int d = lane; d < DD; d += 32) {
        float xv = xr[d];
        float4 w = *(const float4*)&Wf[(size_t)d * 4];
        a0 += xv * w.x; a1 += xv * w.y; a2 += xv * w.z; a3 += xv * w.w;
    }
#pragma unroll
    for (int o = 16; o > 0; o >>= 1) {
        a0 += __shfl_xor_sync(0xffffffffu, a0, o);
        a1 += __shfl_xor_sync(0xffffffffu, a1, o);
        a2 += __shfl_xor_sync(0xffffffffu, a2, o);
        a3 += __shfl_xor_sync(0xffffffffu, a3, o);
    }
    if (lane == 0) {
        float l[4] = {a0 + bf[0], a1 + bf[1], a2 + bf[2], a3 + bf[3]};
        int i1 = 0;
#pragma unroll
        for (int e = 1; e < 4; e++) if (l[e] > l[i1]) i1 = e;
        int i2 = (i1 == 0) ? 1 : 0;
#pragma unroll
        for (int e = 0; e < 4; e++) if (e != i1 && l[e] > l[i2]) i2 = e;
        float p2 = expf(l[i2] - l[i1]);
        float s  = 1.0f + p2;
        float g1 = 1.0f / s;
        float g2 = p2 / s;

        int p = atomicAdd(&cnt[i1], 1);
        idxL[i1 * TT + p]  = tok;
        gateL[i1 * TT + p] = g1;
        p = atomicAdd(&cnt[i2], 1);
        idxL[i2 * TT + p]  = tok;
        gateL[i2 * TT + p] = g2;
    }
}

// ============================================================================
// FP16 tensor-core GEMM v5b: same schedule/layout as validated tf32 v4
// (256 thr, 8 warps 4m x 2n, warp tile 32x64, CTA 128x128, double-buffered
// cp.async, stride-80B smem rows, identical ldmatrix byte addressing) with
// f16 elements: 16B row-chunk = k8 halves -> stage covers BK=32, m16n8k16
// mma (half the instruction count of tf32 at the same 10-bit mantissa).
//   A:  [rows x K] f16 token rows, optionally gathered via idxL
//   Bt: [N x K]    f16 weight transposed
// NOTE: aE is the per-expert stride of A in **u16 elements** (R15 bug:
// passed u32 units -> experts 1-3 read garbage). cE is in u32 elements
// (applied to the packed-f16x2 output pointer).
// EPI 0: C(f16x2)[r][c] = v + bias                         (proj -> h)
// EPI 1: C(f16x2)[r][c] = gelu(v + bias)                   (GEMM1 -> act)
// EPI 2: out(f32)[idx[r]][c] += gate[r]*(v + bias), red.v2 (GEMM2 -> out)
// EBATCH: blockIdx.z = expert, offsets Bt/bias/idxL/gateL/count and A or C.
// ============================================================================
template<bool GATHER, int EPI, bool EBATCH>
__global__ __launch_bounds__(256) void gemm_f16_v5(
    const uint16_t* __restrict__ A, const uint16_t* __restrict__ Bt,
    const float* __restrict__ bias,
    const int* __restrict__ idxL, const float* __restrict__ gateL,
    const int* __restrict__ countp,
    void* __restrict__ Cv, int N, int K, size_t aE, size_t cE)
{
    __shared__ uint32_t As[2][128][20];    // 128 rows x (64B data = k32 f16 + 16B pad)
    __shared__ uint32_t Bs[2][128][20];

    if (EBATCH) {
        const int e = blockIdx.z;
        Bt     += (size_t)e * K * N;
        bias   += (size_t)e * N;
        idxL   += e * TT;
        gateL  += e * TT;
        countp += e;
        A      += (size_t)e * aE;           // aE in u16 elements
    }
    uint32_t* Cu = (uint32_t*)Cv;          // packed f16x2 output (EPI 0/1)
    float*    Cf = (float*)Cv;             // f32 output (EPI 2)
    if (EBATCH && EPI == 1) Cu += (size_t)blockIdx.z * cE;   // cE in u32 elements

    const int count = *countp;
    const int bm = blockIdx.y * 128;
    if (bm >= count) return;
    const int bn = blockIdx.x * 128;

    const int tid  = threadIdx.x;
    const int warp = tid >> 5, lane = tid & 31;
    const int g    = lane >> 2, tig = lane & 3;
    const int wm   = (warp >> 1) * 32;   // 0,32,64,96
    const int wn   = (warp & 1) * 64;    // 0,64

    float c[2][8][4];
#pragma unroll
    for (int mt = 0; mt < 2; mt++)
#pragma unroll
        for (int nt = 0; nt < 8; nt++)
#pragma unroll
            for (int i = 0; i < 4; i++) c[mt][nt][i] = 0.0f;

    // ---- cp.async fill mapping ----
    const int fRow = tid >> 2, fSeg = tid & 3;        // 128 rows x 4 16B-segs
    int arow0 = bm + fRow, arow1 = arow0 + 64;
    if (GATHER) { arow0 = idxL[arow0]; arow1 = idxL[arow1]; }   // pads -> token 0
    const uint16_t* aG0 = A  + (size_t)arow0 * K + fSeg * 8;    // 16B = 8 halves
    const uint16_t* aG1 = A  + (size_t)arow1 * K + fSeg * 8;
    const uint16_t* bG0 = Bt + (size_t)(bn + fRow) * K + fSeg * 8;
    const uint16_t* bG1 = bG0 + (size_t)64 * K;

    const uint32_t smA = smem_u32(&As[0][0][0]);
    const uint32_t smB = smem_u32(&Bs[0][0][0]);
    const uint32_t fOff = (uint32_t)(fRow * 80 + fSeg * 16);
    const uint32_t sA0 = smA + fOff, sA1 = sA0 + 64 * 80;
    const uint32_t sB0 = smB + fOff, sB1 = sB0 + 64 * 80;
    const uint32_t stageB = 128 * 20 * 4;   // 10240 B per stage

    // ---- ldmatrix per-lane addresses (byte-identical mapping to v4) ----
    const int lane7 = lane & 7;
    const uint32_t aRowL = ((lane >> 3) & 1) * 8 + lane7;
    const uint32_t aColB = (lane >> 4) * 16;          // k-half group (16B)
    const uint32_t bRowL = (lane >> 4) * 8 + lane7;
    const uint32_t bColB = ((lane >> 3) & 1) * 16;
    uint32_t aAddr[2], bAddr[4];
#pragma unroll
    for (int mt = 0; mt < 2; mt++)
        aAddr[mt] = smA + (wm + mt * 16 + aRowL) * 80 + aColB;
#pragma unroll
    for (int p = 0; p < 4; p++)
        bAddr[p] = smB + (wn + p * 16 + bRowL) * 80 + bColB;

    const int KT = K >> 5;                  // BK = 32 (f16)

    // prologue: issue tile 0 into stage 0
    CP_ASYNC16(sA0, aG0);
    CP_ASYNC16(sA1, aG1);
    CP_ASYNC16(sB0, bG0);
    CP_ASYNC16(sB1, bG1);
    CP_COMMIT();

    for (int kt = 0; kt < KT; kt++) {
        const int cur = kt & 1;
        CP_WAIT_ALL();           // tile kt resident in stage cur
        __syncthreads();         // all warps done with stage cur^1

        if (kt + 1 < KT) {       // issue tile kt+1 into stage cur^1 (overlaps mma)
            const uint32_t nbO = (cur ^ 1) * stageB;
            CP_ASYNC16(sA0 + nbO, aG0 + (kt + 1) * 32);
            CP_ASYNC16(sA1 + nbO, aG1 + (kt + 1) * 32);
            CP_ASYNC16(sB0 + nbO, bG0 + (kt + 1) * 32);
            CP_ASYNC16(sB1 + nbO, bG1 + (kt + 1) * 32);
            CP_COMMIT();
        }

        const uint32_t stO = cur * stageB;
#pragma unroll
        for (int ks = 0; ks < 2; ks++) {    // two k16 steps per stage
            const uint32_t kO = stO + ks * 32;
            uint32_t af[2][4], bf[8][2];
#pragma unroll
            for (int mt = 0; mt < 2; mt++)
                LDSM_X4(af[mt][0], af[mt][1], af[mt][2], af[mt][3],
                        aAddr[mt] + kO);
#pragma unroll
            for (int p = 0; p < 4; p++)
                LDSM_X4(bf[2 * p][0], bf[2 * p][1], bf[2 * p + 1][0], bf[2 * p + 1][1],
                        bAddr[p] + kO);
#pragma unroll
            for (int mt = 0; mt < 2; mt++)
#pragma unroll
                for (int nt = 0; nt < 8; nt++)
                    mma_f16(c[mt][nt], af[mt], bf[nt]);
        }
    }

    // ---- epilogue ----
#pragma unroll
    for (int mt = 0; mt < 2; mt++) {
        int rc0 = bm + wm + mt * 16 + g;
        int rc1 = rc0 + 8;
        bool v0 = true, v1 = true;
        int row0 = rc0, row1 = rc1;
        float s0 = 1.0f, s1 = 1.0f;
        if (EPI == 2) {
            v0 = rc0 < count;
            v1 = rc1 < count;
            row0 = v0 ? idxL[rc0] : 0;
            row1 = v1 ? idxL[rc1] : 0;
            s0 = v0 ? gateL[rc0] : 0.0f;
            s1 = v1 ? gateL[rc1] : 0.0f;
        }
#pragma unroll
        for (int nt = 0; nt < 8; nt++) {
            int c0 = bn + wn + nt * 8 + tig * 2;        // even column
            float b0v = bias[c0], b1v = bias[c0 + 1];
            float v00 = c[mt][nt][0] + b0v;
            float v01 = c[mt][nt][1] + b1v;
            float v10 = c[mt][nt][2] + b0v;
            float v11 = c[mt][nt][3] + b1v;
            if (EPI == 0) {
                Cu[((size_t)row0 * N + c0) >> 1] = pack_f16x2(v00, v01);
                Cu[((size_t)row1 * N + c0) >> 1] = pack_f16x2(v10, v11);
            } else if (EPI == 1) {
                Cu[((size_t)row0 * N + c0) >> 1] =
                    pack_f16x2(gelu_tanh(v00), gelu_tanh(v01));
                Cu[((size_t)row1 * N + c0) >> 1] =
                    pack_f16x2(gelu_tanh(v10), gelu_tanh(v11));
            } else {
                if (v0) red_add_v2(Cf + (size_t)row0 * N + c0, s0 * v00, s0 * v01);
                if (v1) red_add_v2(Cf + (size_t)row1 * N + c0, s1 * v10, s1 * v11);
            }
        }
    }
}

// ============================================================================
// launch
// ============================================================================
extern "C" void kernel_launch(void* const* d_in, const int* in_sizes, int n_in,
                              void* d_out, int out_size)
{
    const float* X  = (const float*)d_in[0];   // [8,2048,768]
    const float* W  = (const float*)d_in[1];   // [768,768]
    const float* b  = (const float*)d_in[2];   // [768]
    const float* Wg = (const float*)d_in[3];   // [768,4]
    const float* bg = (const float*)d_in[4];   // [4]
    const float* W1 = (const float*)d_in[5];   // [4,768,1024]
    const float* b1 = (const float*)d_in[6];   // [4,1024]
    const float* W2 = (const float*)d_in[7];   // [4,1024,768]
    const float* b2 = (const float*)d_in[8];   // [4,768]
    float* out = (float*)d_out;

    const int T = in_sizes[0] / DD;            // 16384

    uint32_t *Xh, *h, *act;
    uint16_t *Wt, *W1t, *W2t;
    float *gate, *Wf, *bf;
    int *idx, *cnt;
    cudaGetSymbolAddress((void**)&Xh,   g_Xh);
    cudaGetSymbolAddress((void**)&h,    g_h);
    cudaGetSymbolAddress((void**)&act,  g_act);
    cudaGetSymbolAddress((void**)&Wt,   g_Wt);
    cudaGetSymbolAddress((void**)&W1t,  g_W1t);
    cudaGetSymbolAddress((void**)&W2t,  g_W2t);
    cudaGetSymbolAddress((void**)&idx,  g_idx);
    cudaGetSymbolAddress((void**)&gate, g_gate);
    cudaGetSymbolAddress((void**)&cnt,  g_cnt);
    cudaGetSymbolAddress((void**)&Wf,   g_Wf);
    cudaGetSymbolAddress((void**)&bf,   g_bf);

    // 0) zero output (red.v2-accumulated) and routing state
    cudaMemsetAsync(out, 0, sizeof(float) * (size_t)T * DD);
    init_kernel<<<(EE * TT + 255) / 256, 256>>>(cnt, idx, gate);

    // 1) operand prep: X -> f16; weights -> transposed [n][k] f16
    {
        size_t nX = (size_t)T * DD / 4;
        tofp16_kernel<<<(unsigned)((nX + 255) / 256), 256>>>(X, Xh, nX);
        transpose_f16_kernel<<<dim3(DD / 32, DD / 32, 1), 256>>>(
            W, Wt, DD, DD, 0, 0);
        transpose_f16_kernel<<<dim3(DFFC / 32, DD / 32, EE), 256>>>(
            W1, W1t, DD, DFFC, (size_t)DD * DFFC, (size_t)DFFC * DD);
        transpose_f16_kernel<<<dim3(DD / 32, DFFC / 32, EE), 256>>>(
            W2, W2t, DFFC, DD, (size_t)DFFC * DD, (size_t)DD * DFFC);
    }

    // 2) fused router weights + router (fp32 logits straight from X)
    fuse_wg_kernel<<<(DD + 1 + 7) / 8, 256>>>(W, Wg, b, bg, Wf, bf);
    router_kernel<<<T / 8, 256>>>(X, Wf, bf, idx, gate, cnt, T);

    // 3) projection h = X @ W + b      (dense, EPI0 writes f16x2)
    gemm_f16_v5<false, 0, false>
        <<<dim3(DD / 128, T / 128), 256>>>(
            (const uint16_t*)Xh, Wt, b, idx, gate, cnt + EE, h, DD, DD, 0, 0);

    // 4) GEMM1 (all experts): act[e][rc] = f16(gelu(h[idx[rc]] @ W1[e] + b1[e]))
    //    cE in u32 elements (packed f16x2 slice stride)
    gemm_f16_v5<true, 1, true>
        <<<dim3(DFFC / 128, T / 128, EE), 256>>>(
            (const uint16_t*)h, W1t, b1, idx, gate, cnt, act, DFFC, DD,
            0, (size_t)TT * DFFC / 2);

    // 5) GEMM2 (all experts): out[idx[rc]] += gate[rc]*(act[e][rc] @ W2[e] + b2[e])
    //    aE in u16 elements (FIX: was TT*DFFC/2 = u32 units -> wrong slices)
    gemm_f16_v5<false, 2, true>
        <<<dim3(DD / 128, T / 128, EE), 256>>>(
            (const uint16_t*)act, W2t, b2, idx, gate, cnt, out, DD, DFFC,
            (size_t)TT * DFFC, 0);
}